// round 8
// baseline (speedup 1.0000x reference)
#include <cuda_runtime.h>
#include <cstdint>

// ---------------- problem constants ----------------
#define M_DIM 8192
#define K_DIM 4096
#define N_DIM 16384

#define BM 128
#define BN 128
#define BKC 128                      // K elems (int8) per pipeline chunk
#define NCHUNK (K_DIM / BKC)         // 32
#define STAGES 4

#define TILE_B 16384                 // 128 rows x 128B
#define STAGE_B (3 * TILE_B)         // Aq1 + Aq2 + Wq = 49152

#define SMEM_TILE0 1024
#define SMEM_TOTAL (SMEM_TILE0 + STAGES * STAGE_B)   // 197632

#define MT_M (M_DIM / BM)            // 64
#define MT_N (N_DIM / BN)            // 128
#define THREADS 288                  // 8 compute warps + 1 producer warp

// ---------------- scratch ----------------
// Aq1/Aq2: [mt(64)][chunk(32)] 128x128 int8 SW128 blocks, 16KB each (32MB each)
// Wq:      [nt(128)][chunk(32)] 128x128 int8 SW128 blocks, 16KB each (64MB)
__device__ uint8_t g_Aq1[(size_t)M_DIM * K_DIM];
__device__ uint8_t g_Aq2[(size_t)M_DIM * K_DIM];
__device__ uint8_t g_Wq [(size_t)N_DIM * K_DIM];
__device__ float2  g_sA [M_DIM];     // {inv1 = 1/s1, s1}

// ---------------- PTX helpers ----------------
__device__ __forceinline__ uint32_t smem_u32(const void* p) {
    uint32_t a;
    asm("{ .reg .u64 t; cvta.to.shared.u64 t, %1; cvt.u32.u64 %0, t; }" : "=r"(a) : "l"(p));
    return a;
}
#define MBAR_INIT(addr, cnt) \
    asm volatile("mbarrier.init.shared.b64 [%0], %1;" :: "r"(addr), "r"(cnt) : "memory")
#define MBAR_EXPECT_TX(addr, bytes) \
    asm volatile("mbarrier.arrive.expect_tx.shared.b64 _, [%0], %1;" :: "r"(addr), "r"(bytes) : "memory")
#define MBAR_ARRIVE(addr) \
    asm volatile("mbarrier.arrive.shared.b64 _, [%0];" :: "r"(addr) : "memory")
#define MBAR_WAIT(addr, ph) do {                                                  \
    uint32_t _m = (addr), _p = (ph), _d;                                          \
    asm volatile("{ .reg .pred p; mbarrier.try_wait.parity.acquire.cta.shared::cta.b64 p, [%1], %2; selp.b32 %0,1,0,p; }" \
                 : "=r"(_d) : "r"(_m), "r"(_p) : "memory");                       \
    if (!_d) {                                                                    \
        asm volatile("{ .reg .pred P1; WL%=: mbarrier.try_wait.parity.acquire.cta.shared::cta.b64 P1, [%0], %1, 0x989680; @P1 bra.uni WD%=; bra.uni WL%=; WD%=: }" \
                     :: "r"(_m), "r"(_p) : "memory");                             \
    } } while (0)

__device__ __forceinline__ void bulk_g2s(uint32_t dst, const void* src, uint32_t bytes, uint32_t mbar) {
    asm volatile("cp.async.bulk.shared::cluster.global.mbarrier::complete_tx::bytes [%0], [%1], %2, [%3];"
                 :: "r"(dst), "l"(src), "r"(bytes), "r"(mbar) : "memory");
}
__device__ __forceinline__ void ldsm4(uint32_t* r, uint32_t addr) {
    asm volatile("ldmatrix.sync.aligned.m8n8.x4.shared.b16 {%0,%1,%2,%3}, [%4];"
                 : "=r"(r[0]), "=r"(r[1]), "=r"(r[2]), "=r"(r[3]) : "r"(addr));
}
__device__ __forceinline__ void imma(int* c, const uint32_t* a, uint32_t b0, uint32_t b1) {
    asm volatile(
        "mma.sync.aligned.m16n8k32.row.col.s32.s8.s8.s32 "
        "{%0,%1,%2,%3},{%4,%5,%6,%7},{%8,%9},{%0,%1,%2,%3};"
        : "+r"(c[0]), "+r"(c[1]), "+r"(c[2]), "+r"(c[3])
        : "r"(a[0]), "r"(a[1]), "r"(a[2]), "r"(a[3]), "r"(b0), "r"(b1));
}
__device__ __forceinline__ uint32_t swz128(uint32_t off) { return off ^ ((off >> 3) & 0x70); }
__device__ __forceinline__ int clamp127(int v) { return max(-127, min(127, v)); }

// ---------------- pre-pass 1: per-row amax of A ----------------
__global__ void __launch_bounds__(128) rowAmax(const float* __restrict__ A) {
    __shared__ float red[4];
    const int row = blockIdx.x;
    const float4* p = (const float4*)(A + (size_t)row * K_DIM);
    float m = 0.0f;
#pragma unroll
    for (int i = 0; i < 8; i++) {
        float4 v = p[threadIdx.x + i * 128];
        m = fmaxf(m, fmaxf(fmaxf(fabsf(v.x), fabsf(v.y)), fmaxf(fabsf(v.z), fabsf(v.w))));
    }
#pragma unroll
    for (int o = 16; o > 0; o >>= 1) m = fmaxf(m, __shfl_xor_sync(0xFFFFFFFF, m, o));
    if ((threadIdx.x & 31) == 0) red[threadIdx.x >> 5] = m;
    __syncthreads();
    if (threadIdx.x == 0) {
        m = fmaxf(fmaxf(red[0], red[1]), fmaxf(red[2], red[3]));
        m = fmaxf(m, 1e-20f);
        g_sA[row] = make_float2(127.0f / m, m / 127.0f);
    }
}

// ---------------- pre-pass 2: quantize A -> q1,q2 swizzled blocks ----------------
__global__ void __launch_bounds__(256) quantA(const float* __restrict__ A) {
    uint32_t u = blockIdx.x * 256u + threadIdx.x;      // M*K/8 units
    uint32_t m = u >> 9;
    uint32_t k0 = (u & 511u) << 3;
    const float4* p = (const float4*)(A + ((size_t)m << 12) + k0);
    float4 f0 = p[0], f1 = p[1];
    float fv[8] = {f0.x, f0.y, f0.z, f0.w, f1.x, f1.y, f1.z, f1.w};
    float2 sc = g_sA[m];
    const float inv1 = sc.x, s1 = sc.y, inv2 = sc.x * 254.0f;
    uint32_t p1[2] = {0, 0}, p2[2] = {0, 0};
#pragma unroll
    for (int j = 0; j < 8; j++) {
        int q1 = clamp127(__float2int_rn(fv[j] * inv1));
        float r = fmaf(-s1, (float)q1, fv[j]);
        int q2 = clamp127(__float2int_rn(r * inv2));
        p1[j >> 2] |= ((uint32_t)q1 & 0xFFu) << ((j & 3) * 8);
        p2[j >> 2] |= ((uint32_t)q2 & 0xFFu) << ((j & 3) * 8);
    }
    uint32_t off = swz128((m & 127u) * 128u + (k0 & 127u));
    size_t blk = ((size_t)(m >> 7) * NCHUNK + (k0 >> 7)) * TILE_B;
    *(uint2*)(g_Aq1 + blk + off) = make_uint2(p1[0], p1[1]);
    *(uint2*)(g_Aq2 + blk + off) = make_uint2(p2[0], p2[1]);
}

// ---------------- pre-pass 3: pack W int32 -> int8 swizzled blocks ----------------
__global__ void __launch_bounds__(256) quantW(const int* __restrict__ W) {
    uint32_t u = blockIdx.x * 256u + threadIdx.x;      // N*K/8 units
    uint32_t n = u >> 9;
    uint32_t k0 = (u & 511u) << 3;
    const int4* p = (const int4*)(W + ((size_t)n << 12) + k0);
    int4 w0 = p[0], w1 = p[1];
    uint32_t a = ((uint32_t)w0.x & 0xFF) | (((uint32_t)w0.y & 0xFF) << 8) |
                 (((uint32_t)w0.z & 0xFF) << 16) | (((uint32_t)w0.w & 0xFF) << 24);
    uint32_t b = ((uint32_t)w1.x & 0xFF) | (((uint32_t)w1.y & 0xFF) << 8) |
                 (((uint32_t)w1.z & 0xFF) << 16) | (((uint32_t)w1.w & 0xFF) << 24);
    uint32_t off = swz128((n & 127u) * 128u + (k0 & 127u));
    size_t blk = ((size_t)(n >> 7) * NCHUNK + (k0 >> 7)) * TILE_B;
    *(uint2*)(g_Wq + blk + off) = make_uint2(a, b);
}

// ---------------- main GEMM: int8 IMMA x2 + bulk-async pipeline ----------------
__global__ void __launch_bounds__(THREADS, 1)
gemm_imma(const float* __restrict__ wscale, const float* __restrict__ bias,
          float* __restrict__ Out) {
    extern __shared__ char smem[];
    const uint32_t sb = smem_u32(smem);
    const int tid = threadIdx.x, warp = tid >> 5, lane = tid & 31;

    // rasterize: groups of 8 m-tiles, n fastest (L2-friendly)
    const int l  = blockIdx.x & 1023;         // 8 * 128
    const int gq = blockIdx.x >> 10;
    const int mt = gq * 8 + (l & 7);
    const int nt = l >> 3;
    const int m0 = mt * BM, n0 = nt * BN;

    if (tid == 0) {
#pragma unroll
        for (int s = 0; s < STAGES; s++) {
            MBAR_INIT(sb + 16 * s, 1);        // full[s]
            MBAR_INIT(sb + 16 * s + 8, 8);    // empty[s]
        }
    }
    __syncthreads();

    if (warp == 8) {
        // ---------------- producer warp ----------------
        const char* bA1 = (const char*)g_Aq1 + (size_t)mt * NCHUNK * TILE_B;
        const char* bA2 = (const char*)g_Aq2 + (size_t)mt * NCHUNK * TILE_B;
        const char* bW  = (const char*)g_Wq  + (size_t)nt * NCHUNK * TILE_B;
        int s = 0, ph = 1;
        for (int c = 0; c < NCHUNK; c++) {
            MBAR_WAIT(sb + 16 * s + 8, (uint32_t)ph);
            if (lane == 0) {
                uint32_t full = sb + 16 * s;
                uint32_t td = sb + SMEM_TILE0 + s * STAGE_B;
                MBAR_EXPECT_TX(full, (uint32_t)STAGE_B);
                bulk_g2s(td,              bA1 + (size_t)c * TILE_B, TILE_B, full);
                bulk_g2s(td + TILE_B,     bA2 + (size_t)c * TILE_B, TILE_B, full);
                bulk_g2s(td + 2 * TILE_B, bW  + (size_t)c * TILE_B, TILE_B, full);
            }
            if (++s == STAGES) { s = 0; ph ^= 1; }
        }
        return;
    }

    // ---------------- compute warps 0..7 : warp tile 32m x 64n ----------------
    const int warp_m = warp & 3;
    const int warp_n = warp >> 2;
    const int wm0 = warp_m * 32;
    const int wn0 = warp_n * 64;

    // int8 ldmatrix per-lane addressing (byte cols, 128B rows)
    const int rA = lane & 15;                       // A row within 16
    const int cA = (lane >> 4) * 16;                // A byte col 0/16
    const int rB = (lane & 7) | ((lane & 16) >> 1); // B row within 16
    const int cB = ((lane >> 3) & 1) * 16;          // B byte col 0/16

    uint32_t rowOffA[2], rowOffB[4];
#pragma unroll
    for (int t = 0; t < 2; t++) rowOffA[t] = (wm0 + t * 16 + rA) * 128;
#pragma unroll
    for (int q = 0; q < 4; q++) rowOffB[q] = (wn0 + q * 16 + rB) * 128;
    const uint32_t swzA = (rA & 7) << 4;
    const uint32_t swzB = (rB & 7) << 4;

    int acch[2][8][4], accl[2][8][4];
#pragma unroll
    for (int t = 0; t < 2; t++)
#pragma unroll
        for (int n8 = 0; n8 < 8; n8++)
#pragma unroll
            for (int i = 0; i < 4; i++) { acch[t][n8][i] = 0; accl[t][n8][i] = 0; }

    int s = 0, ph = 0;
    for (int c = 0; c < NCHUNK; c++) {
        MBAR_WAIT(sb + 16 * s, (uint32_t)ph);
        const uint32_t sA1 = sb + SMEM_TILE0 + s * STAGE_B;
        const uint32_t sA2 = sA1 + TILE_B;
        const uint32_t sW  = sA1 + 2 * TILE_B;

#pragma unroll
        for (int ks = 0; ks < 4; ks++) {
            const uint32_t colA = ((uint32_t)(ks * 32 + cA)) ^ swzA;
            const uint32_t colB = ((uint32_t)(ks * 32 + cB)) ^ swzB;
            uint32_t ah[2][4], al[2][4], bf[2][4];
#pragma unroll
            for (int t = 0; t < 2; t++) {
                ldsm4(ah[t], sA1 + rowOffA[t] + colA);
                ldsm4(al[t], sA2 + rowOffA[t] + colA);
            }
            ldsm4(bf[0], sW + rowOffB[0] + colB);
#pragma unroll
            for (int q = 0; q < 4; q++) {
                if (q < 3) ldsm4(bf[(q + 1) & 1], sW + rowOffB[q + 1] + colB);
                const uint32_t* b = bf[q & 1];
#pragma unroll
                for (int t = 0; t < 2; t++) {
                    imma(acch[t][2 * q],     ah[t], b[0], b[1]);
                    imma(acch[t][2 * q + 1], ah[t], b[2], b[3]);
                    imma(accl[t][2 * q],     al[t], b[0], b[1]);
                    imma(accl[t][2 * q + 1], al[t], b[2], b[3]);
                }
            }
        }
        if (lane == 0) MBAR_ARRIVE(sb + 16 * s + 8);
        if (++s == STAGES) { s = 0; ph ^= 1; }
    }

    // ---------------- epilogue: out = (s1*hi + s2*lo) * wscale + bias ----------------
    const int groupID = lane >> 2, tig = lane & 3;
#pragma unroll
    for (int t = 0; t < 2; t++) {
        const int gm0 = m0 + wm0 + t * 16 + groupID;
        const float s1a = g_sA[gm0].y,     s2a = s1a * (1.0f / 254.0f);
        const float s1b = g_sA[gm0 + 8].y, s2b = s1b * (1.0f / 254.0f);
#pragma unroll
        for (int n8 = 0; n8 < 8; n8++) {
            const int gn = n0 + wn0 + n8 * 8 + tig * 2;
            const float w0 = wscale[gn], w1 = wscale[gn + 1];
            const float b0 = bias[gn],   b1 = bias[gn + 1];
            float2 o1, o2;
            float v;
            v = fmaf((float)acch[t][n8][0], s1a, (float)accl[t][n8][0] * s2a);
            o1.x = fmaf(v, w0, b0);
            v = fmaf((float)acch[t][n8][1], s1a, (float)accl[t][n8][1] * s2a);
            o1.y = fmaf(v, w1, b1);
            v = fmaf((float)acch[t][n8][2], s1b, (float)accl[t][n8][2] * s2b);
            o2.x = fmaf(v, w0, b0);
            v = fmaf((float)acch[t][n8][3], s1b, (float)accl[t][n8][3] * s2b);
            o2.y = fmaf(v, w1, b1);
            *(float2*)(Out + (size_t)gm0 * N_DIM + gn)       = o1;
            *(float2*)(Out + (size_t)(gm0 + 8) * N_DIM + gn) = o2;
        }
    }
}

// ---------------- launch ----------------
extern "C" void kernel_launch(void* const* d_in, const int* in_sizes, int n_in,
                              void* d_out, int out_size) {
    const float* input  = (const float*)d_in[0];   // [B,S,K] fp32
    const int*   weight = (const int*)d_in[1];     // [N,K] int32
    const float* wscale = (const float*)d_in[2];   // [N]
    const float* bias   = (const float*)d_in[3];   // [N]
    float* out = (float*)d_out;

    rowAmax<<<M_DIM, 128>>>(input);
    quantA<<<(M_DIM * K_DIM / 8) / 256, 256>>>(input);    // 16384 blocks
    quantW<<<(N_DIM * K_DIM / 8) / 256, 256>>>(weight);   // 32768 blocks

    cudaFuncSetAttribute(gemm_imma, cudaFuncAttributeMaxDynamicSharedMemorySize, SMEM_TOTAL);
    gemm_imma<<<MT_M * MT_N, THREADS, SMEM_TOTAL>>>(wscale, bias, out);
}

// round 10
// speedup vs baseline: 6.2897x; 6.2897x over previous
#include <cuda_runtime.h>
#include <cuda_fp16.h>
#include <cstdint>

// ---------------- problem constants ----------------
#define M_DIM 8192
#define K_DIM 4096
#define N_DIM 16384

#define BM 128
#define BN 128
#define BKC 64                       // K elems per pipeline chunk
#define NCHUNK (K_DIM / BKC)         // 64
#define STAGES 3

#define A_TILE_B 16384               // 128 rows x 128B (64 fp16)
#define W_TILE_B 16384               // 128 rows x 128B
#define STAGE_B (A_TILE_B + W_TILE_B)        // 32768

#define SMEM_TILE0 1024
#define SMEM_TOTAL (SMEM_TILE0 + STAGES * STAGE_B)   // 99328 -> 2 CTAs/SM

#define MT_M (M_DIM / BM)            // 64
#define MT_N (N_DIM / BN)            // 128
#define THREADS 288                  // 8 compute warps + 1 producer warp

// ---------------- scratch: pre-swizzled fp16 tile blocks ----------------
__device__ __half g_A[(size_t)M_DIM * K_DIM];
__device__ __half g_W[(size_t)N_DIM * K_DIM];

// ---------------- PTX helpers ----------------
__device__ __forceinline__ uint32_t smem_u32(const void* p) {
    uint32_t a;
    asm("{ .reg .u64 t; cvta.to.shared.u64 t, %1; cvt.u32.u64 %0, t; }" : "=r"(a) : "l"(p));
    return a;
}
#define MBAR_INIT(addr, cnt) \
    asm volatile("mbarrier.init.shared.b64 [%0], %1;" :: "r"(addr), "r"(cnt) : "memory")
#define MBAR_EXPECT_TX(addr, bytes) \
    asm volatile("mbarrier.arrive.expect_tx.shared.b64 _, [%0], %1;" :: "r"(addr), "r"(bytes) : "memory")
#define MBAR_ARRIVE(addr) \
    asm volatile("mbarrier.arrive.shared.b64 _, [%0];" :: "r"(addr) : "memory")
#define MBAR_WAIT(addr, ph) do {                                                  \
    uint32_t _m = (addr), _p = (ph), _d;                                          \
    asm volatile("{ .reg .pred p; mbarrier.try_wait.parity.acquire.cta.shared::cta.b64 p, [%1], %2; selp.b32 %0,1,0,p; }" \
                 : "=r"(_d) : "r"(_m), "r"(_p) : "memory");                       \
    if (!_d) {                                                                    \
        asm volatile("{ .reg .pred P1; WL%=: mbarrier.try_wait.parity.acquire.cta.shared::cta.b64 P1, [%0], %1, 0x989680; @P1 bra.uni WD%=; bra.uni WL%=; WD%=: }" \
                     :: "r"(_m), "r"(_p) : "memory");                             \
    } } while (0)

__device__ __forceinline__ void bulk_g2s(uint32_t dst, const void* src, uint32_t bytes, uint32_t mbar) {
    asm volatile("cp.async.bulk.shared::cluster.global.mbarrier::complete_tx::bytes [%0], [%1], %2, [%3];"
                 :: "r"(dst), "l"(src), "r"(bytes), "r"(mbar) : "memory");
}
__device__ __forceinline__ void ldsm4(uint32_t* r, uint32_t addr) {
    asm volatile("ldmatrix.sync.aligned.m8n8.x4.shared.b16 {%0,%1,%2,%3}, [%4];"
                 : "=r"(r[0]), "=r"(r[1]), "=r"(r[2]), "=r"(r[3]) : "r"(addr));
}
__device__ __forceinline__ void mma_f16(float* c, const uint32_t* a, uint32_t b0, uint32_t b1) {
    asm volatile(
        "mma.sync.aligned.m16n8k16.row.col.f32.f16.f16.f32 "
        "{%0,%1,%2,%3},{%4,%5,%6,%7},{%8,%9},{%0,%1,%2,%3};"
        : "+f"(c[0]), "+f"(c[1]), "+f"(c[2]), "+f"(c[3])
        : "r"(a[0]), "r"(a[1]), "r"(a[2]), "r"(a[3]), "r"(b0), "r"(b1));
}
__device__ __forceinline__ uint32_t swz128(uint32_t off) { return off ^ ((off >> 3) & 0x70); }
__device__ __forceinline__ uint32_t pack_h2(float a, float b) {
    __half2 t = __floats2half2_rn(a, b);
    return *(uint32_t*)&t;
}

// ---------------- pre-pass: A fp32 -> fp16 swizzled 128-row tile blocks ----------------
__global__ void __launch_bounds__(256) convertA(const float* __restrict__ A) {
    uint32_t u = blockIdx.x * 256u + threadIdx.x;      // M*K/8 units
    uint32_t m = u >> 9;
    uint32_t k0 = (u & 511u) << 3;
    const float4* p = (const float4*)(A + ((size_t)m << 12) + k0);
    float4 f0 = p[0], f1 = p[1];
    uint4 o;
    o.x = pack_h2(f0.x, f0.y); o.y = pack_h2(f0.z, f0.w);
    o.z = pack_h2(f1.x, f1.y); o.w = pack_h2(f1.z, f1.w);
    uint32_t off = swz128((m & 127u) * 128u + (k0 & 63u) * 2u);
    size_t blk = ((size_t)(m >> 7) * NCHUNK + (k0 >> 6)) * A_TILE_B;
    *(uint4*)((char*)g_A + blk + off) = o;
}

// ---------------- pre-pass: W int32 -> fp16 swizzled 128-row tile blocks ----------------
__global__ void __launch_bounds__(256) convertW(const int* __restrict__ W) {
    uint32_t u = blockIdx.x * 256u + threadIdx.x;      // N*K/8 units
    uint32_t n = u >> 9;
    uint32_t k0 = (u & 511u) << 3;
    const int4* p = (const int4*)(W + ((size_t)n << 12) + k0);
    int4 w0 = p[0], w1 = p[1];
    uint4 o;
    o.x = pack_h2((float)w0.x, (float)w0.y);
    o.y = pack_h2((float)w0.z, (float)w0.w);
    o.z = pack_h2((float)w1.x, (float)w1.y);
    o.w = pack_h2((float)w1.z, (float)w1.w);
    uint32_t off = swz128((n & 127u) * 128u + (k0 & 63u) * 2u);
    size_t blk = ((size_t)(n >> 7) * NCHUNK + (k0 >> 6)) * W_TILE_B;
    *(uint4*)((char*)g_W + blk + off) = o;
}

// ---------------- main GEMM: mma.sync + ldmatrix + bulk-async, 2 CTAs/SM ----------------
__global__ void __launch_bounds__(THREADS, 2)
gemm_mma(const float* __restrict__ wscale, const float* __restrict__ bias,
         float* __restrict__ Out) {
    extern __shared__ char smem[];
    const uint32_t sb = smem_u32(smem);
    const int tid = threadIdx.x, warp = tid >> 5, lane = tid & 31;

    // rasterize: groups of 8 m-tiles, n fastest (L2-friendly)
    const int l  = blockIdx.x & 1023;         // 8 * 128
    const int gq = blockIdx.x >> 10;
    const int mt = gq * 8 + (l & 7);
    const int nt = l >> 3;
    const int m0 = mt * BM, n0 = nt * BN;

    if (tid == 0) {
#pragma unroll
        for (int s = 0; s < STAGES; s++) {
            MBAR_INIT(sb + 16 * s, 1);        // full[s] (tx-based)
            MBAR_INIT(sb + 16 * s + 8, 8);    // empty[s] (8 compute warps, lane0)
        }
    }
    __syncthreads();

    if (warp == 8) {
        // ---------------- producer warp ----------------
        const char* bA = (const char*)g_A + (size_t)mt * NCHUNK * A_TILE_B;
        const char* bW = (const char*)g_W + (size_t)nt * NCHUNK * W_TILE_B;
        int s = 0, ph = 1;
        for (int c = 0; c < NCHUNK; c++) {
            MBAR_WAIT(sb + 16 * s + 8, (uint32_t)ph);
            if (lane == 0) {
                uint32_t full = sb + 16 * s;
                uint32_t td = sb + SMEM_TILE0 + s * STAGE_B;
                MBAR_EXPECT_TX(full, (uint32_t)STAGE_B);
                bulk_g2s(td,            bA + (size_t)c * A_TILE_B, A_TILE_B, full);
                bulk_g2s(td + A_TILE_B, bW + (size_t)c * W_TILE_B, W_TILE_B, full);
            }
            if (++s == STAGES) { s = 0; ph ^= 1; }
        }
        return;
    }

    // ---------------- compute warps 0..7 : warp tile 32m x 64n ----------------
    const int warp_m = warp & 3;              // 4
    const int warp_n = warp >> 2;             // 2
    const int wm0 = warp_m * 32;
    const int wn0 = warp_n * 64;

    // ldmatrix per-lane address components (verified mapping)
    const int rA = lane & 15;                       // A row within 16
    const int cA = (lane >> 4) * 8;                 // A col 0/8
    const int rB = (lane & 7) | ((lane & 16) >> 1); // B row within 16
    const int cB = ((lane >> 3) & 1) * 8;           // B col 0/8

    uint32_t rowOffA[2], rowOffB[4];
#pragma unroll
    for (int t = 0; t < 2; t++) rowOffA[t] = (wm0 + t * 16 + rA) * 128;
#pragma unroll
    for (int q = 0; q < 4; q++) rowOffB[q] = (wn0 + q * 16 + rB) * 128;
    const uint32_t swzA = (rA & 7) << 4;
    const uint32_t swzB = (rB & 7) << 4;

    float acc[2][8][4];
#pragma unroll
    for (int t = 0; t < 2; t++)
#pragma unroll
        for (int n8 = 0; n8 < 8; n8++)
#pragma unroll
            for (int i = 0; i < 4; i++) acc[t][n8][i] = 0.0f;

    int s = 0, ph = 0;
    for (int c = 0; c < NCHUNK; c++) {
        MBAR_WAIT(sb + 16 * s, (uint32_t)ph);
        const uint32_t sA = sb + SMEM_TILE0 + s * STAGE_B;
        const uint32_t sW = sA + A_TILE_B;
#pragma unroll
        for (int ks = 0; ks < 4; ks++) {
            const uint32_t colA = (((uint32_t)(ks * 16 + cA)) * 2u) ^ swzA;
            const uint32_t colB = (((uint32_t)(ks * 16 + cB)) * 2u) ^ swzB;
            uint32_t af[2][4], bf[4][4];
#pragma unroll
            for (int t = 0; t < 2; t++) ldsm4(af[t], sA + rowOffA[t] + colA);
#pragma unroll
            for (int q = 0; q < 4; q++) ldsm4(bf[q], sW + rowOffB[q] + colB);
#pragma unroll
            for (int t = 0; t < 2; t++)
#pragma unroll
                for (int n8 = 0; n8 < 8; n8++) {
                    const uint32_t* b = bf[n8 >> 1];
                    if (n8 & 1) mma_f16(acc[t][n8], af[t], b[2], b[3]);
                    else        mma_f16(acc[t][n8], af[t], b[0], b[1]);
                }
        }
        if (lane == 0) MBAR_ARRIVE(sb + 16 * s + 8);
        if (++s == STAGES) { s = 0; ph ^= 1; }
    }

    // ---------------- epilogue: out = acc * scale[n] + bias[n] ----------------
    const int groupID = lane >> 2, tig = lane & 3;
#pragma unroll
    for (int t = 0; t < 2; t++) {
        const int gm0 = m0 + wm0 + t * 16 + groupID;
#pragma unroll
        for (int n8 = 0; n8 < 8; n8++) {
            const int gn = n0 + wn0 + n8 * 8 + tig * 2;
            const float s0 = wscale[gn], s1 = wscale[gn + 1];
            const float b0 = bias[gn],   b1 = bias[gn + 1];
            float2 o1, o2;
            o1.x = fmaf(acc[t][n8][0], s0, b0);
            o1.y = fmaf(acc[t][n8][1], s1, b1);
            o2.x = fmaf(acc[t][n8][2], s0, b0);
            o2.y = fmaf(acc[t][n8][3], s1, b1);
            *(float2*)(Out + (size_t)gm0 * N_DIM + gn)       = o1;
            *(float2*)(Out + (size_t)(gm0 + 8) * N_DIM + gn) = o2;
        }
    }
}

// ---------------- launch ----------------
extern "C" void kernel_launch(void* const* d_in, const int* in_sizes, int n_in,
                              void* d_out, int out_size) {
    const float* input  = (const float*)d_in[0];   // [B,S,K] fp32
    const int*   weight = (const int*)d_in[1];     // [N,K] int32
    const float* wscale = (const float*)d_in[2];   // [N]
    const float* bias   = (const float*)d_in[3];   // [N]
    float* out = (float*)d_out;

    convertA<<<(M_DIM * K_DIM / 8) / 256, 256>>>(input);   // 16384 blocks
    convertW<<<(N_DIM * K_DIM / 8) / 256, 256>>>(weight);  // 32768 blocks

    cudaFuncSetAttribute(gemm_mma, cudaFuncAttributeMaxDynamicSharedMemorySize, SMEM_TOTAL);
    gemm_mma<<<MT_M * MT_N, THREADS, SMEM_TOTAL>>>(wscale, bias, out);
}